// round 17
// baseline (speedup 1.0000x reference)
#include <cuda_runtime.h>
#include <cuda_fp16.h>
#include <stdint.h>

#define Bq 256
#define Hq 128
#define Nq 2048
#define BM 128
#define BN 128
#define BK 32
#define BS2 136          // Bs16[.][k2][n] stride in half2 (conflict-free)
#define GRIDY 18

// dynamic smem offsets (bytes)
#define OFF_A   0                       // 128 x 128 half2, swizzled: 65536
#define OFF_B   65536                   // 2 x 16 x 136 x 4 = 17408
#define OFF_VS  (OFF_B + 17408)         // 82944: 128 floats
#define OFF_CS  (OFF_VS + 512)          // 83456: 128 floats
#define OFF_RED (OFF_CS + 512)          // 83968: 4 x 128 floats
#define SMEM_TOTAL (OFF_RED + 2048)     // 86016

// Packed+swizzled W GEMM-slice image (matches smem A layout exactly):
// (h, col): dst = h*128 + ((col>>2)^(h&7))*4 + (col&3); value = half2(W[h][2col], W[h][2col+1])
__device__ __align__(16) uint32_t g_Wp[Hq * 128];
// Precomputed bias: g_bias[b*128+h] = W[h][256:384] . dec[b]
__device__ float g_bias[Bq * Hq];

// ---------------- helpers ----------------
__device__ __forceinline__ float tanh_fast(float x) {
    float y; asm("tanh.approx.f32 %0, %1;" : "=f"(y) : "f"(x)); return y;
}
__device__ __forceinline__ void mma16(float* c, const uint32_t* a, const uint32_t* b) {
    asm volatile(
        "mma.sync.aligned.m16n8k16.row.col.f32.f16.f16.f32 "
        "{%0,%1,%2,%3}, {%4,%5,%6,%7}, {%8,%9}, {%0,%1,%2,%3};"
        : "+f"(c[0]), "+f"(c[1]), "+f"(c[2]), "+f"(c[3])
        : "r"(a[0]), "r"(a[1]), "r"(a[2]), "r"(a[3]), "r"(b[0]), "r"(b[1]));
}
__device__ __forceinline__ uint32_t pack2(float lo, float hi) {
    uint32_t r;
    asm("cvt.rn.f16x2.f32 %0, %2, %1;" : "=r"(r) : "f"(lo), "f"(hi));
    return r;
}
__device__ __forceinline__ void cpa16(uint32_t dst_smem, const void* src) {
    asm volatile("cp.async.ca.shared.global [%0], [%1], 16;"
                 :: "r"(dst_smem), "l"(src) : "memory");
}

// ---------------------------------------------------------------------------
// Kernel 0: prep. Blocks 0..63: pack W[:,0:256] -> swizzled fp16 image.
//           Blocks 64..319: bias[b][h] = W[h][256:384] . dec[b].
// ---------------------------------------------------------------------------
__global__ void prep_kernel(const float* __restrict__ W,
                            const float* __restrict__ dec) {
    const int bid = blockIdx.x;
    const int t = threadIdx.x;
    if (bid < 64) {
        const int i = bid * 256 + t;            // 0..16383
        const int col = i & 127;
        const int h   = i >> 7;
        const float2 wv = *(const float2*)&W[h * 384 + 2 * col];
        const int dst = h * 128 + (((col >> 2) ^ (h & 7)) << 2) + (col & 3);
        g_Wp[dst] = pack2(wv.x, wv.y);
    } else {
        const int b = bid - 64;
        __shared__ float dsh[Hq];
        const int w = t >> 5, lane = t & 31;
        if (t < Hq) dsh[t] = dec[b * Hq + t];
        __syncthreads();
#pragma unroll
        for (int r = 0; r < 16; r++) {
            const int h = w * 16 + r;
            float p = 0.f;
#pragma unroll
            for (int i = 0; i < 4; i++)
                p = fmaf(W[h * 384 + 256 + lane + 32 * i], dsh[lane + 32 * i], p);
#pragma unroll
            for (int off = 16; off; off >>= 1)
                p += __shfl_xor_sync(0xffffffffu, p, off);
            if (lane == 0) g_bias[b * Hq + h] = p;
        }
    }
}

// ---------------------------------------------------------------------------
// Kernel 1: batch-persistent fp16 HMMA GEMM + tanh/v-dot -> raw scores
// A image resident in smem; B pipeline with PREFETCH DISTANCE 2 (two register
// sets): LDG(c+2) issues at chunk c, consumed ~1.5 chunk-walls later.
// grid (16, 18), 256 threads, dyn smem 86016 B, occ 2.
// ---------------------------------------------------------------------------
__global__ __launch_bounds__(256, 2) void score_kernel(
    const float* __restrict__ st, const float* __restrict__ dy,
    const float* __restrict__ v, float* __restrict__ out) {
    extern __shared__ __align__(16) char smem[];
    float* vs  = (float*)(smem + OFF_VS);
    float* cs  = (float*)(smem + OFF_CS);
    float* red = (float*)(smem + OFF_RED);
    const uint32_t* A32 = (const uint32_t*)(smem + OFF_A);
    __half2* Bs16 = (__half2*)(smem + OFF_B);   // [2][16][BS2]

    const int n0 = blockIdx.x * BN;
    const int by = blockIdx.y;
    const int nb     = (by < 4) ? 15 : 14;
    const int bstart = (by < 4) ? by * 15 : 60 + (by - 4) * 14;

    const int t  = threadIdx.x;
    const int w  = t >> 5;
    const int lane = t & 31;
    const int wm = w & 3;
    const int wn = w >> 2;
    const int gid = lane >> 2;
    const int tig = lane & 3;

    // ---- one-time A image load ----
    {
        const uint32_t sbA = (uint32_t)__cvta_generic_to_shared(smem + OFF_A);
        const char* gA = (const char*)g_Wp;
#pragma unroll
        for (int i = 0; i < 16; i++)
            cpa16(sbA + (t + 256 * i) * 16, gA + (t + 256 * i) * 16);
        asm volatile("cp.async.commit_group;" ::: "memory");
    }
    if (t < Hq) vs[t] = v[t];

    // B loader indices (loop-invariant)
    const int bk0 = t >> 5, bc = t & 31;
    const int bk1 = (t + 256) >> 5;

    for (int bi = 0; bi < nb; bi++) {
        const int b = bstart + bi;
        const float* base_st = st + (size_t)b * Hq * Nq;
        const float* base_dy = dy + (size_t)b * Hq * Nq;

        if (t < Hq) cs[t] = g_bias[b * Hq + t];

        // pb[set][slot][rowpair]; set s holds chunk data, sets ping-pong
        float4 pb[2][2][2];

        // ---- prologue: LDG chunks 0,1 (both in static region); STS chunk 0 ----
#pragma unroll
        for (int s = 0; s < 2; s++) {
            const float* s0 = base_st + (size_t)(s * BK + 2 * bk0) * Nq + n0 + bc * 4;
            const float* s1 = base_st + (size_t)(s * BK + 2 * bk1) * Nq + n0 + bc * 4;
            pb[s][0][0] = *(const float4*)s0;  pb[s][0][1] = *(const float4*)(s0 + Nq);
            pb[s][1][0] = *(const float4*)s1;  pb[s][1][1] = *(const float4*)(s1 + Nq);
        }
        {
            uint4 b0, b1;
            b0.x = pack2(pb[0][0][0].x, pb[0][0][1].x); b0.y = pack2(pb[0][0][0].y, pb[0][0][1].y);
            b0.z = pack2(pb[0][0][0].z, pb[0][0][1].z); b0.w = pack2(pb[0][0][0].w, pb[0][0][1].w);
            b1.x = pack2(pb[0][1][0].x, pb[0][1][1].x); b1.y = pack2(pb[0][1][0].y, pb[0][1][1].y);
            b1.z = pack2(pb[0][1][0].z, pb[0][1][1].z); b1.w = pack2(pb[0][1][0].w, pb[0][1][1].w);
            *(uint4*)&Bs16[(0 * 16 + bk0) * BS2 + bc * 4] = b0;
            *(uint4*)&Bs16[(0 * 16 + bk1) * BS2 + bc * 4] = b1;
        }
        if (bi == 0) asm volatile("cp.async.wait_group 0;" ::: "memory");
        __syncthreads();

        float acc[2][8][4];
#pragma unroll
        for (int i = 0; i < 2; i++)
#pragma unroll
            for (int j = 0; j < 8; j++)
#pragma unroll
                for (int q = 0; q < 4; q++) acc[i][j][q] = 0.f;

        for (int c = 0; c < 8; c++) {
            const int cur = c & 1, nxt = cur ^ 1;

            // ---- LDG chunk c+2 into the set freed last chunk (distance 2) ----
            if (c < 6) {
                const int gk0 = (c + 2) * BK + 2 * bk0;
                const int gk1 = (c + 2) * BK + 2 * bk1;
                const float* s0 = (gk0 < Hq ? base_st + (size_t)gk0 * Nq
                                            : base_dy + (size_t)(gk0 - Hq) * Nq) + n0 + bc * 4;
                const float* s1 = (gk1 < Hq ? base_st + (size_t)gk1 * Nq
                                            : base_dy + (size_t)(gk1 - Hq) * Nq) + n0 + bc * 4;
                pb[cur][0][0] = *(const float4*)s0;  pb[cur][0][1] = *(const float4*)(s0 + Nq);
                pb[cur][1][0] = *(const float4*)s1;  pb[cur][1][1] = *(const float4*)(s1 + Nq);
            }

            // ---- MMA: A frags from resident swizzled image, B from Bs16 ----
            const __half2* Bb = Bs16 + cur * (16 * BS2);
#pragma unroll
            for (int kf = 0; kf < 2; kf++) {
                const int Q0 = c * 4 + kf * 2;
                const int x0 = ((Q0 ^ gid) << 2) + tig;
                const int x1 = (((Q0 + 1) ^ gid) << 2) + tig;
                uint32_t a[2][4], bb[8][2];
#pragma unroll
                for (int mf = 0; mf < 2; mf++) {
                    const int h0 = wm * 32 + mf * 16 + gid;   // h0&7 == gid
                    a[mf][0] = A32[h0 * 128 + x0];
                    a[mf][1] = A32[(h0 + 8) * 128 + x0];
                    a[mf][2] = A32[h0 * 128 + x1];
                    a[mf][3] = A32[(h0 + 8) * 128 + x1];
                }
                const int k2 = kf * 8;
#pragma unroll
                for (int nf = 0; nf < 8; nf++) {
                    const int n = wn * 64 + nf * 8;
                    bb[nf][0] = *(const uint32_t*)&Bb[(k2 + tig) * BS2 + n + gid];
                    bb[nf][1] = *(const uint32_t*)&Bb[(k2 + tig + 4) * BS2 + n + gid];
                }
#pragma unroll
                for (int mf = 0; mf < 2; mf++)
#pragma unroll
                    for (int nf = 0; nf < 8; nf++)
                        mma16(acc[mf][nf], a[mf], bb[nf]);
            }

            // ---- pack + STS chunk c+1 (data arrived ~1.5 walls ago) ----
            if (c < 7) {
                uint4 b0, b1;
                b0.x = pack2(pb[nxt][0][0].x, pb[nxt][0][1].x);
                b0.y = pack2(pb[nxt][0][0].y, pb[nxt][0][1].y);
                b0.z = pack2(pb[nxt][0][0].z, pb[nxt][0][1].z);
                b0.w = pack2(pb[nxt][0][0].w, pb[nxt][0][1].w);
                b1.x = pack2(pb[nxt][1][0].x, pb[nxt][1][1].x);
                b1.y = pack2(pb[nxt][1][0].y, pb[nxt][1][1].y);
                b1.z = pack2(pb[nxt][1][0].z, pb[nxt][1][1].z);
                b1.w = pack2(pb[nxt][1][0].w, pb[nxt][1][1].w);
                *(uint4*)&Bs16[(nxt * 16 + bk0) * BS2 + bc * 4] = b0;
                *(uint4*)&Bs16[(nxt * 16 + bk1) * BS2 + bc * 4] = b1;
            }
            __syncthreads();
        }

        // ---- epilogue: tanh + v-dot, reduce over m ----
#pragma unroll
        for (int nf = 0; nf < 8; nf++) {
            float p0 = 0.f, p1 = 0.f;
#pragma unroll
            for (int mf = 0; mf < 2; mf++) {
                const int r0 = wm * 32 + mf * 16 + gid;
                const int r1 = r0 + 8;
                const float v0 = vs[r0], c0 = cs[r0];
                const float v1 = vs[r1], c1 = cs[r1];
                p0 = fmaf(v0, tanh_fast(acc[mf][nf][0] + c0), p0);
                p1 = fmaf(v0, tanh_fast(acc[mf][nf][1] + c0), p1);
                p0 = fmaf(v1, tanh_fast(acc[mf][nf][2] + c1), p0);
                p1 = fmaf(v1, tanh_fast(acc[mf][nf][3] + c1), p1);
            }
#pragma unroll
            for (int off = 4; off < 32; off <<= 1) {
                p0 += __shfl_xor_sync(0xffffffffu, p0, off);
                p1 += __shfl_xor_sync(0xffffffffu, p1, off);
            }
            if (gid == 0) {
                const int col = wn * 64 + nf * 8 + 2 * tig;
                red[wm * BN + col]     = p0;
                red[wm * BN + col + 1] = p1;
            }
        }
        __syncthreads();

        if (t < BN)
            out[(size_t)b * Nq + n0 + t] =
                red[t] + red[BN + t] + red[2 * BN + t] + red[3 * BN + t];
    }
}

// ---------------------------------------------------------------------------
// Kernel 2: in-place row softmax over N=2048
// ---------------------------------------------------------------------------
__global__ __launch_bounds__(256) void softmax_kernel(float* __restrict__ out) {
    __shared__ float sm[8];
    const int b = blockIdx.x, t = threadIdx.x;
    const int w = t >> 5, lane = t & 31;
    float* row = out + (size_t)b * Nq;

    float vals[8];
    float m = -1e30f;
#pragma unroll
    for (int i = 0; i < 8; i++) { vals[i] = row[t + 256 * i]; m = fmaxf(m, vals[i]); }
#pragma unroll
    for (int off = 16; off; off >>= 1)
        m = fmaxf(m, __shfl_xor_sync(0xffffffffu, m, off));
    if (lane == 0) sm[w] = m;
    __syncthreads();
    float M = sm[lane & 7];
#pragma unroll
    for (int off = 4; off; off >>= 1)
        M = fmaxf(M, __shfl_xor_sync(0xffffffffu, M, off));

    float sum = 0.f;
#pragma unroll
    for (int i = 0; i < 8; i++) { vals[i] = __expf(vals[i] - M); sum += vals[i]; }
#pragma unroll
    for (int off = 16; off; off >>= 1)
        sum += __shfl_xor_sync(0xffffffffu, sum, off);
    __syncthreads();
    if (lane == 0) sm[w] = sum;
    __syncthreads();
    float S = sm[lane & 7];
#pragma unroll
    for (int off = 4; off; off >>= 1)
        S += __shfl_xor_sync(0xffffffffu, S, off);

    const float inv = 1.f / S;
#pragma unroll
    for (int i = 0; i < 8; i++) row[t + 256 * i] = vals[i] * inv;
}

// ---------------------------------------------------------------------------
extern "C" void kernel_launch(void* const* d_in, const int* in_sizes, int n_in,
                              void* d_out, int out_size) {
    const float* st  = (const float*)d_in[0];
    const float* dy  = (const float*)d_in[1];
    const float* dec = (const float*)d_in[2];
    const float* v   = (const float*)d_in[3];
    const float* W   = (const float*)d_in[4];
    float* out = (float*)d_out;

    cudaFuncSetAttribute(score_kernel,
                         cudaFuncAttributeMaxDynamicSharedMemorySize, SMEM_TOTAL);

    prep_kernel<<<64 + Bq, 256>>>(W, dec);
    score_kernel<<<dim3(Nq / BN, GRIDY), 256, SMEM_TOTAL>>>(st, dy, v, out);
    softmax_kernel<<<Bq, 256>>>(out);
}